// round 10
// baseline (speedup 1.0000x reference)
#include <cuda_runtime.h>
#include <math.h>
#include <stdint.h>

#define Bsz 16
#define Ssz 512
#define Dsz 1024
#define Hh  16
#define Ff  4096
#define DH  64
#define MROWS (Bsz*Ssz)   // 8192

// ---------------- scratch (device-global; no allocation allowed) -------------
__device__ float g_X[MROWS*Dsz];
__device__ float g_Q[MROWS*Dsz];
__device__ float g_K[MROWS*Dsz];
__device__ float g_V[MROWS*Dsz];
__device__ float g_C[MROWS*Dsz];
__device__ float g_T[MROWS*Dsz];
__device__ float g_Hb[MROWS*Ff];

// ---------------- helpers ----------------------------------------------------
__device__ __forceinline__ uint32_t f2tf32(float x) {
    uint32_t u;
    asm("cvt.rna.tf32.f32 %0, %1;" : "=r"(u) : "f"(x));
    return u;
}
__device__ __forceinline__ void mma_tf32(float& c0, float& c1, float& c2, float& c3,
                                         uint32_t a0, uint32_t a1, uint32_t a2, uint32_t a3,
                                         uint32_t b0, uint32_t b1) {
    asm volatile(
        "mma.sync.aligned.m16n8k8.row.col.f32.tf32.tf32.f32 "
        "{%0,%1,%2,%3}, {%4,%5,%6,%7}, {%8,%9}, {%0,%1,%2,%3};"
        : "+f"(c0), "+f"(c1), "+f"(c2), "+f"(c3)
        : "r"(a0), "r"(a1), "r"(a2), "r"(a3), "r"(b0), "r"(b1));
}

// ---------------- staged-cvt TF32 mma.sync GEMM ------------------------------
// C[M,N] = A[M,K] @ W[K,N] + bias (+Res) (+ReLU). fp32 in/out, tf32 mma.
// BM=BN=128, BK=16. Register-prefetch + 2-stage smem; cvt done ONCE at staging.
#define APAD 20               // A row stride in words (16 data + 4 pad)
#define BPAD 132              // B row stride in words (128 data + 4 pad)
#define A_W  (128*APAD)       // 2560 words
#define B_W  (16*BPAD)        // 2112 words
#define STG_W (A_W + B_W)     // 4672 words per stage
#define GEMM_SMEM (2*STG_W*4) // 37376 B

template<bool RELU, bool RES>
__global__ void __launch_bounds__(256, 2)
gemm_pipe(const float* __restrict__ A, const float* __restrict__ Bm,
          const float* __restrict__ bias, const float* __restrict__ Res,
          float* __restrict__ C, int M, int N, int K)
{
    extern __shared__ uint32_t smu[];

    const int tid  = threadIdx.x;
    const int warp = tid >> 5;
    const int lane = tid & 31;
    const int wm   = warp >> 2;        // 0..1
    const int wn   = warp & 3;         // 0..3
    const int g    = lane >> 2;        // 0..7
    const int tg   = lane & 3;         // 0..3

    const int bm = blockIdx.y * 128;
    const int bn = blockIdx.x * 128;
    const int NT = K >> 4;

    // producer mapping (per thread: 2 A float4 + 2 B float4)
    const int arow0 = tid >> 2;            // j=0: rows 0..63
    const int acol  = (tid & 3) * 4;
    const int bkr0  = tid >> 5;            // j=0: k rows 0..7
    const int bnc   = (tid & 31) * 4;

    const float* Ap0 = A  + (size_t)(bm + arow0) * K + acol;
    const float* Ap1 = A  + (size_t)(bm + arow0 + 64) * K + acol;
    const float* Bp0 = Bm + (size_t)bkr0 * N + bn + bnc;
    const float* Bp1 = Bm + (size_t)(bkr0 + 8) * N + bn + bnc;

    // prefetch tile 0 into registers
    float4 ra0 = *(const float4*)Ap0;
    float4 ra1 = *(const float4*)Ap1;
    float4 rb0 = *(const float4*)Bp0;
    float4 rb1 = *(const float4*)Bp1;

    float acc[4][4][4];
    #pragma unroll
    for (int i = 0; i < 4; ++i)
        #pragma unroll
        for (int j = 0; j < 4; ++j)
            #pragma unroll
            for (int e = 0; e < 4; ++e) acc[i][j][e] = 0.f;

    for (int t = 0; t < NT; ++t) {
        // stage registers -> smem (cvt happens here, once per element)
        uint32_t* sA = smu + (t & 1) * STG_W;
        uint32_t* sB = sA + A_W;
        *(uint4*)&sA[arow0 * APAD + acol] =
            make_uint4(f2tf32(ra0.x), f2tf32(ra0.y), f2tf32(ra0.z), f2tf32(ra0.w));
        *(uint4*)&sA[(arow0 + 64) * APAD + acol] =
            make_uint4(f2tf32(ra1.x), f2tf32(ra1.y), f2tf32(ra1.z), f2tf32(ra1.w));
        *(uint4*)&sB[bkr0 * BPAD + bnc] =
            make_uint4(f2tf32(rb0.x), f2tf32(rb0.y), f2tf32(rb0.z), f2tf32(rb0.w));
        *(uint4*)&sB[(bkr0 + 8) * BPAD + bnc] =
            make_uint4(f2tf32(rb1.x), f2tf32(rb1.y), f2tf32(rb1.z), f2tf32(rb1.w));
        __syncthreads();

        // prefetch next tile into registers (overlaps with compute below)
        if (t + 1 < NT) {
            const int k0 = (t + 1) << 4;
            ra0 = *(const float4*)(Ap0 + k0);
            ra1 = *(const float4*)(Ap1 + k0);
            rb0 = *(const float4*)(Bp0 + (size_t)k0 * N);
            rb1 = *(const float4*)(Bp1 + (size_t)k0 * N);
        }

        // compute tile t (no cvt in loop)
        #pragma unroll
        for (int ks = 0; ks < 16; ks += 8) {
            uint32_t af[4][4];
            uint32_t bf[4][2];
            #pragma unroll
            for (int mi = 0; mi < 4; ++mi) {
                const int m0 = wm * 64 + mi * 16 + g;
                af[mi][0] = sA[m0 * APAD + ks + tg];
                af[mi][1] = sA[(m0 + 8) * APAD + ks + tg];
                af[mi][2] = sA[m0 * APAD + ks + tg + 4];
                af[mi][3] = sA[(m0 + 8) * APAD + ks + tg + 4];
            }
            #pragma unroll
            for (int nj = 0; nj < 4; ++nj) {
                const int cn = wn * 32 + nj * 8 + g;
                bf[nj][0] = sB[(ks + tg) * BPAD + cn];
                bf[nj][1] = sB[(ks + tg + 4) * BPAD + cn];
            }
            #pragma unroll
            for (int mi = 0; mi < 4; ++mi)
                #pragma unroll
                for (int nj = 0; nj < 4; ++nj)
                    mma_tf32(acc[mi][nj][0], acc[mi][nj][1], acc[mi][nj][2], acc[mi][nj][3],
                             af[mi][0], af[mi][1], af[mi][2], af[mi][3],
                             bf[nj][0], bf[nj][1]);
        }
        // no second barrier needed: next iter writes the OTHER stage; a stage is
        // rewritten only 2 iters later, past a barrier that post-dates all reads.
    }

    // epilogue: c0,c1 at (row g, col 2tg, 2tg+1); c2,c3 at row g+8
    #pragma unroll
    for (int nj = 0; nj < 4; ++nj) {
        const int col = bn + wn * 32 + nj * 8 + 2 * tg;
        const float2 bi = *(const float2*)&bias[col];
        #pragma unroll
        for (int mi = 0; mi < 4; ++mi) {
            const int r0 = bm + wm * 64 + mi * 16 + g;
            const int r1 = r0 + 8;
            float2 o0 = make_float2(acc[mi][nj][0] + bi.x, acc[mi][nj][1] + bi.y);
            float2 o1 = make_float2(acc[mi][nj][2] + bi.x, acc[mi][nj][3] + bi.y);
            if (RES) {
                float2 q0 = *(const float2*)&Res[(size_t)r0 * N + col];
                float2 q1 = *(const float2*)&Res[(size_t)r1 * N + col];
                o0.x += q0.x; o0.y += q0.y;
                o1.x += q1.x; o1.y += q1.y;
            }
            if (RELU) {
                o0.x = fmaxf(o0.x, 0.f); o0.y = fmaxf(o0.y, 0.f);
                o1.x = fmaxf(o1.x, 0.f); o1.y = fmaxf(o1.y, 0.f);
            }
            *(float2*)&C[(size_t)r0 * N + col] = o0;
            *(float2*)&C[(size_t)r1 * N + col] = o1;
        }
    }
}

// ---------------- flash attention: BQ=32, 3 CTAs/SM target -------------------
// grid: (S/32, B*H), 256 threads. Warp w owns q-rows w*4..w*4+3.
// Lane owns keys {lane, lane+32}; O cols: lane covers rows (w*4+2p, +1), cols colA..+3.
#define ATT_RS 68
#define ATT_SMEM ((192*ATT_RS + 32) * 4)   // 52352 B

__global__ void __launch_bounds__(256, 3)
attn_kernel(const float* __restrict__ Qg, const float* __restrict__ Kg,
            const float* __restrict__ Vg, float* __restrict__ Cg)
{
    extern __shared__ float sm[];
    float* Qs = sm;                    // 32 rows
    float* Ks = sm + 32 * ATT_RS;      // 64 rows
    float* Vs = sm + 96 * ATT_RS;      // 64 rows
    float* Ps = sm + 160 * ATT_RS;     // 32 rows
    float* Cs = sm + 192 * ATT_RS;     // 32 scalars

    const int tid  = threadIdx.x;
    const int w    = tid >> 5;
    const int lane = tid & 31;
    const int qt   = blockIdx.x;         // 0..15
    const int bh   = blockIdx.y;         // 0..255
    const int b    = bh >> 4;
    const int h    = bh & 15;

    const size_t headoff = ((size_t)b * Ssz * Hh + h) * DH;
    const int sstride = Hh * DH;         // 1024 floats per sequence step

    // load Q tile [32 x 64]
    #pragma unroll
    for (int i = 0; i < 2; ++i) {
        int idx = tid + i * 256;         // 0..511
        int r = idx >> 4, c4 = (idx & 15) * 4;
        *(float4*)&Qs[r * ATT_RS + c4] =
            *(const float4*)&Qg[headoff + (size_t)(qt * 32 + r) * sstride + c4];
    }

    float m[4], lden[4];
    #pragma unroll
    for (int r = 0; r < 4; ++r) { m[r] = -1e30f; lden[r] = 0.f; }
    float o0[4], o1[4];
    #pragma unroll
    for (int c = 0; c < 4; ++c) { o0[c] = 0.f; o1[c] = 0.f; }

    const int row0 = w * 4 + ((lane >> 4) << 1);  // this lane's O rows (row0, row0+1)
    const int colA = (lane & 15) * 4;             // O cols colA..colA+3

    for (int kb = 0; kb < 8; ++kb) {
        __syncthreads();     // prior-iter smem reads done (covers Q load at kb=0)
        #pragma unroll
        for (int i = 0; i < 4; ++i) {
            int idx = tid + i * 256;
            int r = idx >> 4, c4 = (idx & 15) * 4;
            size_t gg = headoff + (size_t)(kb * 64 + r) * sstride + c4;
            *(float4*)&Ks[r * ATT_RS + c4] = *(const float4*)&Kg[gg];
            *(float4*)&Vs[r * ATT_RS + c4] = *(const float4*)&Vg[gg];
        }
        __syncthreads();

        // scores: rows w*4..+3 vs keys lane, lane+32
        float s0[4], s1[4];
        #pragma unroll
        for (int r = 0; r < 4; ++r) { s0[r] = 0.f; s1[r] = 0.f; }
        #pragma unroll
        for (int d4 = 0; d4 < 64; d4 += 4) {
            float4 k0 = *(const float4*)&Ks[lane * ATT_RS + d4];
            float4 k1 = *(const float4*)&Ks[(lane + 32) * ATT_RS + d4];
            #pragma unroll
            for (int r = 0; r < 4; ++r) {
                float4 q = *(const float4*)&Qs[(w * 4 + r) * ATT_RS + d4];
                s0[r] += q.x * k0.x + q.y * k0.y + q.z * k0.z + q.w * k0.w;
                s1[r] += q.x * k1.x + q.y * k1.y + q.z * k1.z + q.w * k1.w;
            }
        }

        // online softmax per row (all lanes hold uniform m/l copies)
        #pragma unroll
        for (int r = 0; r < 4; ++r) {
            float sa = s0[r] * 0.125f;
            float sb = s1[r] * 0.125f;
            float mx = fmaxf(sa, sb);
            #pragma unroll
            for (int off = 16; off; off >>= 1)
                mx = fmaxf(mx, __shfl_xor_sync(0xffffffffu, mx, off));
            float mnew = fmaxf(m[r], mx);
            float p0 = __expf(sa - mnew);
            float p1 = __expf(sb - mnew);
            float ps = p0 + p1;
            #pragma unroll
            for (int off = 16; off; off >>= 1)
                ps += __shfl_xor_sync(0xffffffffu, ps, off);
            float corr = __expf(m[r] - mnew);
            lden[r] = lden[r] * corr + ps;
            m[r] = mnew;
            Ps[(w * 4 + r) * ATT_RS + lane]      = p0;
            Ps[(w * 4 + r) * ATT_RS + lane + 32] = p1;
            if (lane == 0) Cs[w * 4 + r] = corr;
        }
        __syncwarp();

        float cr0 = Cs[row0];
        float cr1 = Cs[row0 + 1];
        #pragma unroll
        for (int c = 0; c < 4; ++c) { o0[c] *= cr0; o1[c] *= cr1; }

        // O += P @ V  (warp-private Ps rows, shared Vs)
        #pragma unroll
        for (int kk4 = 0; kk4 < 64; kk4 += 4) {
            float4 pv0 = *(const float4*)&Ps[row0 * ATT_RS + kk4];
            float4 pv1 = *(const float4*)&Ps[(row0 + 1) * ATT_RS + kk4];
            float pa[4] = {pv0.x, pv0.y, pv0.z, pv0.w};
            float pb[4] = {pv1.x, pv1.y, pv1.z, pv1.w};
            #pragma unroll
            for (int j = 0; j < 4; ++j) {
                float4 va = *(const float4*)&Vs[(kk4 + j) * ATT_RS + colA];
                o0[0] += pa[j] * va.x; o0[1] += pa[j] * va.y;
                o0[2] += pa[j] * va.z; o0[3] += pa[j] * va.w;
                o1[0] += pb[j] * va.x; o1[1] += pb[j] * va.y;
                o1[2] += pb[j] * va.z; o1[3] += pb[j] * va.w;
            }
        }
        __syncwarp();   // Ps/Cs reads done before next-iter rewrite by this warp
    }

    // finalize: divide by l, write ctx
    if (lane == 0) {
        #pragma unroll
        for (int r = 0; r < 4; ++r) Cs[w * 4 + r] = lden[r];
    }
    __syncwarp();
    float inv0 = 1.f / Cs[row0];
    float inv1 = 1.f / Cs[row0 + 1];

    size_t base0 = headoff + (size_t)(qt * 32 + row0) * sstride;
    size_t base1 = base0 + sstride;
    float4 out;
    out.x = o0[0]*inv0; out.y = o0[1]*inv0; out.z = o0[2]*inv0; out.w = o0[3]*inv0;
    *(float4*)&Cg[base0 + colA] = out;
    out.x = o1[0]*inv1; out.y = o1[1]*inv1; out.z = o1[2]*inv1; out.w = o1[3]*inv1;
    *(float4*)&Cg[base1 + colA] = out;
}

// ---------------- LayerNorm ---------------------------------------------------
__device__ __forceinline__ float block_sum(float v, float* red)
{
    #pragma unroll
    for (int off = 16; off; off >>= 1)
        v += __shfl_xor_sync(0xffffffffu, v, off);
    __syncthreads();
    if ((threadIdx.x & 31) == 0) red[threadIdx.x >> 5] = v;
    __syncthreads();
    return red[0]+red[1]+red[2]+red[3]+red[4]+red[5]+red[6]+red[7];
}

__global__ void __launch_bounds__(256)
ln_kernel(const float* __restrict__ X, const float* __restrict__ gw,
          const float* __restrict__ bw, float* __restrict__ Y)
{
    __shared__ float red[8];
    const int row = blockIdx.x;
    const int tid = threadIdx.x;
    const size_t base = (size_t)row * Dsz + tid * 4;

    float4 v = *(const float4*)&X[base];
    float mean = block_sum(v.x + v.y + v.z + v.w, red) * (1.f / Dsz);
    float dx = v.x - mean, dy = v.y - mean, dz = v.z - mean, dw = v.w - mean;
    float var = block_sum(dx*dx + dy*dy + dz*dz + dw*dw, red) * (1.f / Dsz);
    float inv = rsqrtf(var + 1e-6f);

    float4 g4 = *(const float4*)&gw[tid * 4];
    float4 b4 = *(const float4*)&bw[tid * 4];
    float4 o;
    o.x = dx * inv * g4.x + b4.x;
    o.y = dy * inv * g4.y + b4.y;
    o.z = dz * inv * g4.z + b4.z;
    o.w = dw * inv * g4.w + b4.w;
    *(float4*)&Y[base] = o;
}

// ---------------- driver -----------------------------------------------------
extern "C" void kernel_launch(void* const* d_in, const int* in_sizes, int n_in,
                              void* d_out, int out_size)
{
    const float* hid  = (const float*)d_in[0];
    const float* Wq   = (const float*)d_in[1];
    const float* bq   = (const float*)d_in[2];
    const float* Wk   = (const float*)d_in[3];
    const float* bk   = (const float*)d_in[4];
    const float* Wv   = (const float*)d_in[5];
    const float* bv   = (const float*)d_in[6];
    const float* Wp   = (const float*)d_in[7];
    const float* bp   = (const float*)d_in[8];
    const float* g1   = (const float*)d_in[9];
    const float* be1  = (const float*)d_in[10];
    const float* W1   = (const float*)d_in[11];
    const float* b1   = (const float*)d_in[12];
    const float* W2   = (const float*)d_in[13];
    const float* b2   = (const float*)d_in[14];
    const float* g2   = (const float*)d_in[15];
    const float* be2  = (const float*)d_in[16];

    float *pX, *pQ, *pK, *pV, *pC, *pT, *pH;
    cudaGetSymbolAddress((void**)&pX, g_X);
    cudaGetSymbolAddress((void**)&pQ, g_Q);
    cudaGetSymbolAddress((void**)&pK, g_K);
    cudaGetSymbolAddress((void**)&pV, g_V);
    cudaGetSymbolAddress((void**)&pC, g_C);
    cudaGetSymbolAddress((void**)&pT, g_T);
    cudaGetSymbolAddress((void**)&pH, g_Hb);

    cudaFuncSetAttribute(attn_kernel,
                         cudaFuncAttributeMaxDynamicSharedMemorySize, ATT_SMEM);
    cudaFuncSetAttribute(gemm_pipe<false,false>,
                         cudaFuncAttributeMaxDynamicSharedMemorySize, GEMM_SMEM);
    cudaFuncSetAttribute(gemm_pipe<false,true>,
                         cudaFuncAttributeMaxDynamicSharedMemorySize, GEMM_SMEM);
    cudaFuncSetAttribute(gemm_pipe<true,false>,
                         cudaFuncAttributeMaxDynamicSharedMemorySize, GEMM_SMEM);

    const size_t hbytes = sizeof(float) * (size_t)MROWS * Dsz;
    cudaMemcpyAsync(pX, hid, hbytes, cudaMemcpyDeviceToDevice);

    dim3 gD(Dsz / 128, MROWS / 128);   // (8, 64)
    dim3 gF(Ff  / 128, MROWS / 128);   // (32, 64)
    dim3 gA(Ssz / 32, Bsz * Hh);       // (16, 256)

    for (int l = 0; l < 4; ++l) {
        const float* wq = Wq + (size_t)l * Dsz * Dsz;
        const float* wk = Wk + (size_t)l * Dsz * Dsz;
        const float* wv = Wv + (size_t)l * Dsz * Dsz;
        const float* wp = Wp + (size_t)l * Dsz * Dsz;
        const float* w1 = W1 + (size_t)l * Dsz * Ff;
        const float* w2 = W2 + (size_t)l * Ff * Dsz;

        gemm_pipe<false,false><<<gD, 256, GEMM_SMEM>>>(pX, wq, bq + l*Dsz, nullptr, pQ, MROWS, Dsz, Dsz);
        gemm_pipe<false,false><<<gD, 256, GEMM_SMEM>>>(pX, wk, bk + l*Dsz, nullptr, pK, MROWS, Dsz, Dsz);
        gemm_pipe<false,false><<<gD, 256, GEMM_SMEM>>>(pX, wv, bv + l*Dsz, nullptr, pV, MROWS, Dsz, Dsz);

        attn_kernel<<<gA, 256, ATT_SMEM>>>(pQ, pK, pV, pC);

        gemm_pipe<false,true ><<<gD, 256, GEMM_SMEM>>>(pC, wp, bp + l*Dsz, pX, pT, MROWS, Dsz, Dsz);
        ln_kernel<<<MROWS, 256>>>(pT, g1 + l*Dsz, be1 + l*Dsz, pX);

        gemm_pipe<true ,false><<<gF, 256, GEMM_SMEM>>>(pX, w1, b1 + l*Ff, nullptr, pH, MROWS, Ff, Dsz);
        gemm_pipe<false,true ><<<gD, 256, GEMM_SMEM>>>(pH, w2, b2 + l*Dsz, pX, pT, MROWS, Dsz, Ff);
        ln_kernel<<<MROWS, 256>>>(pT, g2 + l*Dsz, be2 + l*Dsz, pX);
    }

    cudaMemcpyAsync((float*)d_out, pX, hbytes, cudaMemcpyDeviceToDevice);
}

// round 11
// speedup vs baseline: 1.5879x; 1.5879x over previous
#include <cuda_runtime.h>
#include <cuda_fp16.h>
#include <math.h>
#include <stdint.h>

#define Bsz 16
#define Ssz 512
#define Dsz 1024
#define Hh  16
#define Ff  4096
#define DH  64
#define MROWS (Bsz*Ssz)   // 8192

// ---------------- scratch (device-global; no allocation allowed) -------------
__device__ float g_X[MROWS*Dsz];
__device__ float g_Q[MROWS*Dsz];
__device__ float g_K[MROWS*Dsz];
__device__ float g_V[MROWS*Dsz];
__device__ float g_C[MROWS*Dsz];
__device__ float g_T[MROWS*Dsz];
__device__ float g_Hb[MROWS*Ff];
__device__ uint32_t g_Ah[MROWS*Ff/2];   // packed half2 activations [M][K/2]
__device__ uint32_t g_Bh[(Ff/2)*Dsz];   // packed half2 weights [K/2][N]

// ---------------- pack kernels ----------------------------------------------
// A: [M][K] fp32 -> [M][K/2] uint32(half2, lo=even k)
__global__ void __launch_bounds__(256)
pack_a(const float* __restrict__ X, uint32_t* __restrict__ Y, int n2)
{
    int idx = blockIdx.x * 256 + threadIdx.x;
    if (idx < n2) {
        float2 v = ((const float2*)X)[idx];
        __half2 h = __floats2half2_rn(v.x, v.y);
        Y[idx] = *(uint32_t*)&h;
    }
}

// W: [K][N] fp32 -> [K/2][N] uint32(half2 of (W[2kp][n], W[2kp+1][n]))
__global__ void __launch_bounds__(256)
pack_w(const float* __restrict__ W, uint32_t* __restrict__ Y, int n2, int nshift)
{
    int idx = blockIdx.x * 256 + threadIdx.x;
    if (idx < n2) {
        int kp = idx >> nshift;
        int n  = idx & ((1 << nshift) - 1);
        size_t base = ((size_t)kp * 2 << nshift) + n;
        float a = W[base];
        float b = W[base + (1 << nshift)];
        __half2 h = __floats2half2_rn(a, b);
        Y[idx] = *(uint32_t*)&h;
    }
}

// ---------------- fp16 mma GEMM (m16n8k16) -----------------------------------
// C[M,N] = A[M,K] @ W[K,N] + bias (+Res) (+ReLU). half2-packed in, fp32 out.
// BM=BN=128, BK=16, 4-stage cp.async, 256 thr = 8 warps (2m x 4n), 64x32 warp.
__device__ __forceinline__ void mma_f16(float& c0, float& c1, float& c2, float& c3,
                                        uint32_t a0, uint32_t a1, uint32_t a2, uint32_t a3,
                                        uint32_t b0, uint32_t b1) {
    asm volatile(
        "mma.sync.aligned.m16n8k16.row.col.f32.f16.f16.f32 "
        "{%0,%1,%2,%3}, {%4,%5,%6,%7}, {%8,%9}, {%0,%1,%2,%3};"
        : "+f"(c0), "+f"(c1), "+f"(c2), "+f"(c3)
        : "r"(a0), "r"(a1), "r"(a2), "r"(a3), "r"(b0), "r"(b1));
}

#define CP_ASYNC16(dst_u32, src_ptr) \
    asm volatile("cp.async.cg.shared.global [%0], [%1], 16;" \
                 :: "r"(dst_u32), "l"(src_ptr))
#define CP_COMMIT()  asm volatile("cp.async.commit_group;" ::: "memory")
#define CP_WAIT2()   asm volatile("cp.async.wait_group 2;" ::: "memory")

__device__ __forceinline__ uint32_t smem_u32(const void* p) {
    uint32_t a;
    asm("{ .reg .u64 t; cvta.to.shared.u64 t, %1; cvt.u32.u64 %0, t; }"
        : "=r"(a) : "l"(p));
    return a;
}

#define APAD 12               // A row stride in words (8 data + 4 pad)
#define BPAD 136              // B row stride in words (128 data + 8 pad)
#define A_W  (128*APAD)       // 1536 words
#define B_W  (8*BPAD)         // 1088 words
#define STG_W (A_W + B_W)     // 2624 words
#define GEMM_SMEM (4*STG_W*4) // 41984 B

template<bool RELU, bool RES>
__global__ void __launch_bounds__(256, 2)
gemm_f16(const uint32_t* __restrict__ A, const uint32_t* __restrict__ Bm,
         const float* __restrict__ bias, const float* __restrict__ Res,
         float* __restrict__ C, int M, int N, int K)
{
    extern __shared__ uint32_t smu[];
    const uint32_t su = smem_u32(smu);

    const int tid  = threadIdx.x;
    const int warp = tid >> 5;
    const int lane = tid & 31;
    const int wm   = warp >> 2;        // 0..1
    const int wn   = warp & 3;         // 0..3
    const int g    = lane >> 2;        // 0..7
    const int tg   = lane & 3;         // 0..3

    const int bm = blockIdx.y * 128;
    const int bn = blockIdx.x * 128;
    const int K2 = K >> 1;
    const int NT = K >> 4;             // BK=16 -> 8 packed words

    // producer mapping: 1 A chunk + 1 B chunk per thread per stage
    const int arow = tid >> 1;                 // 0..127
    const int akc  = (tid & 1) * 4;            // packed-word col 0 or 4
    const int bkr  = tid >> 5;                 // 0..7
    const int bnc  = (lane) * 4;               // 0..124

    const uint32_t* Ap = A  + (size_t)(bm + arow) * K2 + akc;
    const uint32_t* Bp = Bm + (size_t)bkr * N + bn + bnc;

    auto issue_stage = [&](int s) {
        const int bi = s & 3;
        const uint32_t sA = su + (uint32_t)(bi * STG_W) * 4;
        const uint32_t sB = sA + A_W * 4;
        CP_ASYNC16(sA + (uint32_t)(arow * APAD + akc) * 4, Ap + s * 8);
        CP_ASYNC16(sB + (uint32_t)(bkr * BPAD + bnc) * 4, Bp + (size_t)s * 8 * N);
    };

    issue_stage(0); CP_COMMIT();
    issue_stage(1); CP_COMMIT();
    issue_stage(2); CP_COMMIT();

    float acc[4][4][4];
    #pragma unroll
    for (int i = 0; i < 4; ++i)
        #pragma unroll
        for (int j = 0; j < 4; ++j)
            #pragma unroll
            for (int e = 0; e < 4; ++e) acc[i][j][e] = 0.f;

    for (int t = 0; t < NT; ++t) {
        CP_WAIT2();
        __syncthreads();

        if (t + 3 < NT) issue_stage(t + 3);
        CP_COMMIT();

        const uint32_t* sA = smu + (t & 3) * STG_W;
        const uint32_t* sB = sA + A_W;

        uint32_t af[4][4];
        uint32_t bf[4][2];
        #pragma unroll
        for (int mi = 0; mi < 4; ++mi) {
            const int m0 = wm * 64 + mi * 16 + g;
            af[mi][0] = sA[m0 * APAD + tg];            // (g,   k=2tg,2tg+1)
            af[mi][1] = sA[(m0 + 8) * APAD + tg];      // (g+8, k=2tg,2tg+1)
            af[mi][2] = sA[m0 * APAD + tg + 4];        // (g,   k=2tg+8,+9)
            af[mi][3] = sA[(m0 + 8) * APAD + tg + 4];  // (g+8, k=2tg+8,+9)
        }
        #pragma unroll
        for (int nj = 0; nj < 4; ++nj) {
            const int cn = wn * 32 + nj * 8 + g;
            bf[nj][0] = sB[tg * BPAD + cn];            // (k=2tg,2tg+1, n=g)
            bf[nj][1] = sB[(tg + 4) * BPAD + cn];      // (k=2tg+8,+9,  n=g)
        }
        #pragma unroll
        for (int mi = 0; mi < 4; ++mi)
            #pragma unroll
            for (int nj = 0; nj < 4; ++nj)
                mma_f16(acc[mi][nj][0], acc[mi][nj][1], acc[mi][nj][2], acc[mi][nj][3],
                        af[mi][0], af[mi][1], af[mi][2], af[mi][3],
                        bf[nj][0], bf[nj][1]);
    }

    // epilogue: c0,c1 at (row g, col 2tg, 2tg+1); c2,c3 at row g+8
    #pragma unroll
    for (int nj = 0; nj < 4; ++nj) {
        const int col = bn + wn * 32 + nj * 8 + 2 * tg;
        const float2 bi = *(const float2*)&bias[col];
        #pragma unroll
        for (int mi = 0; mi < 4; ++mi) {
            const int r0 = bm + wm * 64 + mi * 16 + g;
            const int r1 = r0 + 8;
            float2 o0 = make_float2(acc[mi][nj][0] + bi.x, acc[mi][nj][1] + bi.y);
            float2 o1 = make_float2(acc[mi][nj][2] + bi.x, acc[mi][nj][3] + bi.y);
            if (RES) {
                float2 q0 = *(const float2*)&Res[(size_t)r0 * N + col];
                float2 q1 = *(const float2*)&Res[(size_t)r1 * N + col];
                o0.x += q0.x; o0.y += q0.y;
                o1.x += q1.x; o1.y += q1.y;
            }
            if (RELU) {
                o0.x = fmaxf(o0.x, 0.f); o0.y = fmaxf(o0.y, 0.f);
                o1.x = fmaxf(o1.x, 0.f); o1.y = fmaxf(o1.y, 0.f);
            }
            *(float2*)&C[(size_t)r0 * N + col] = o0;
            *(float2*)&C[(size_t)r1 * N + col] = o1;
        }
    }
}

// ---------------- flash attention (R9 version, BQ=64) ------------------------
#define ATT_ROWSTRIDE 68
#define ATT_SMEM ((4*64*ATT_ROWSTRIDE + 64) * 4)

__global__ void __launch_bounds__(256)
attn_kernel(const float* __restrict__ Qg, const float* __restrict__ Kg,
            const float* __restrict__ Vg, float* __restrict__ Cg)
{
    extern __shared__ float sm[];
    float* Qs = sm;
    float* Ks = sm + 64 * ATT_ROWSTRIDE;
    float* Vs = sm + 2 * 64 * ATT_ROWSTRIDE;
    float* Ps = sm + 3 * 64 * ATT_ROWSTRIDE;
    float* Cs = sm + 4 * 64 * ATT_ROWSTRIDE;

    const int tid  = threadIdx.x;
    const int w    = tid >> 5;
    const int lane = tid & 31;
    const int qt   = blockIdx.x;
    const int bh   = blockIdx.y;
    const int b    = bh >> 4;
    const int h    = bh & 15;

    const size_t headoff = ((size_t)b * Ssz * Hh + h) * DH;
    const int sstride = Hh * DH;

    #pragma unroll
    for (int i = 0; i < 4; ++i) {
        int idx = tid + i * 256;
        int r = idx >> 4, c4 = (idx & 15) * 4;
        *(float4*)&Qs[r * ATT_ROWSTRIDE + c4] =
            *(const float4*)&Qg[headoff + (size_t)(qt * 64 + r) * sstride + c4];
    }

    float m[8], lden[8];
    #pragma unroll
    for (int r = 0; r < 8; ++r) { m[r] = -1e30f; lden[r] = 0.f; }
    float o0[8], o1[8];
    #pragma unroll
    for (int c = 0; c < 8; ++c) { o0[c] = 0.f; o1[c] = 0.f; }

    const int row0 = w * 8 + ((lane >> 3) << 1);
    const int colA = (lane & 7) * 4;

    for (int kb = 0; kb < 8; ++kb) {
        __syncthreads();
        #pragma unroll
        for (int i = 0; i < 4; ++i) {
            int idx = tid + i * 256;
            int r = idx >> 4, c4 = (idx & 15) * 4;
            size_t gg = headoff + (size_t)(kb * 64 + r) * sstride + c4;
            *(float4*)&Ks[r * ATT_ROWSTRIDE + c4] = *(const float4*)&Kg[gg];
            *(float4*)&Vs[r * ATT_ROWSTRIDE + c4] = *(const float4*)&Vg[gg];
        }
        __syncthreads();

        float s0[8], s1[8];
        #pragma unroll
        for (int r = 0; r < 8; ++r) { s0[r] = 0.f; s1[r] = 0.f; }
        #pragma unroll
        for (int d4 = 0; d4 < 64; d4 += 4) {
            float4 k0 = *(const float4*)&Ks[lane * ATT_ROWSTRIDE + d4];
            float4 k1 = *(const float4*)&Ks[(lane + 32) * ATT_ROWSTRIDE + d4];
            #pragma unroll
            for (int r = 0; r < 8; ++r) {
                float4 q = *(const float4*)&Qs[(w * 8 + r) * ATT_ROWSTRIDE + d4];
                s0[r] += q.x * k0.x + q.y * k0.y + q.z * k0.z + q.w * k0.w;
                s1[r] += q.x * k1.x + q.y * k1.y + q.z * k1.z + q.w * k1.w;
            }
        }

        #pragma unroll
        for (int r = 0; r < 8; ++r) {
            float sa = s0[r] * 0.125f;
            float sb = s1[r] * 0.125f;
            float mx = fmaxf(sa, sb);
            #pragma unroll
            for (int off = 16; off; off >>= 1)
                mx = fmaxf(mx, __shfl_xor_sync(0xffffffffu, mx, off));
            float mnew = fmaxf(m[r], mx);
            float p0 = __expf(sa - mnew);
            float p1 = __expf(sb - mnew);
            float ps = p0 + p1;
            #pragma unroll
            for (int off = 16; off; off >>= 1)
                ps += __shfl_xor_sync(0xffffffffu, ps, off);
            float corr = __expf(m[r] - mnew);
            lden[r] = lden[r] * corr + ps;
            m[r] = mnew;
            Ps[(w * 8 + r) * ATT_ROWSTRIDE + lane]      = p0;
            Ps[(w * 8 + r) * ATT_ROWSTRIDE + lane + 32] = p1;
            if (lane == 0) Cs[w * 8 + r] = corr;
        }
        __syncwarp();

        float cr0 = Cs[row0];
        float cr1 = Cs[row0 + 1];
        #pragma unroll
        for (int c = 0; c < 8; ++c) { o0[c] *= cr0; o1[c] *= cr1; }

        #pragma unroll
        for (int kk4 = 0; kk4 < 64; kk4 += 4) {
            float4 pv0 = *(const float4*)&Ps[row0 * ATT_ROWSTRIDE + kk4];
            float4 pv1 = *(const float4*)&Ps[(row0 + 1) * ATT_ROWSTRIDE + kk4];
            float pa[4] = {pv0.x, pv0.y, pv0.z, pv0.w};
            float pb[4] = {pv1.x, pv1.y, pv1.z, pv1.w};
            #pragma unroll
            for (int j = 0; j < 4; ++j) {
                float4 va = *(const float4*)&Vs[(kk4 + j) * ATT_ROWSTRIDE + colA];
                float4 vb = *(const float4*)&Vs[(kk4 + j) * ATT_ROWSTRIDE + colA + 32];
                o0[0] += pa[j] * va.x; o0[1] += pa[j] * va.y;
                o0[2] += pa[j] * va.z; o0[3] += pa[j] * va.w;
                o0[4] += pa[j] * vb.x; o0[5] += pa[j] * vb.y;
                o0[6] += pa[j] * vb.z; o0[7] += pa[j] * vb.w;
                o1[0] += pb[j] * va.x; o1[1] += pb[j] * va.y;
                o1[2] += pb[j] * va.z; o1[3] += pb[j] * va.w;
                o1[4] += pb[j] * vb.x; o1[5] += pb[j] * vb.y;
                o1[6] += pb[j] * vb.z; o1[7] += pb[j] * vb.w;
            }
        }
        __syncwarp();
    }

    if (lane == 0) {
        #pragma unroll
        for (int r = 0; r < 8; ++r) Cs[w * 8 + r] = lden[r];
    }
    __syncwarp();
    float inv0 = 1.f / Cs[row0];
    float inv1 = 1.f / Cs[row0 + 1];

    size_t base0 = headoff + (size_t)(qt * 64 + row0) * sstride;
    size_t base1 = base0 + sstride;
    float4 out;
    out.x = o0[0]*inv0; out.y = o0[1]*inv0; out.z = o0[2]*inv0; out.w = o0[3]*inv0;
    *(float4*)&Cg[base0 + colA] = out;
    out.x = o0[4]*inv0; out.y = o0[5]*inv0; out.z = o0[6]*inv0; out.w = o0[7]*inv0;
    *(float4*)&Cg[base0 + colA + 32] = out;
    out.x = o1[0]*inv1; out.y = o1[1]*inv1; out.z = o1[2]*inv1; out.w = o1[3]*inv1;
    *(float4*)&Cg[base1 + colA] = out;
    out.x = o1[4]*inv1; out.y = o1[5]*inv1; out.z = o1[6]*inv1; out.w = o1[7]*inv1;
    *(float4*)&Cg[base1 + colA + 32] = out;
}

// ---------------- LayerNorm ---------------------------------------------------
__device__ __forceinline__ float block_sum(float v, float* red)
{
    #pragma unroll
    for (int off = 16; off; off >>= 1)
        v += __shfl_xor_sync(0xffffffffu, v, off);
    __syncthreads();
    if ((threadIdx.x & 31) == 0) red[threadIdx.x >> 5] = v;
    __syncthreads();
    return red[0]+red[1]+red[2]+red[3]+red[4]+red[5]+red[6]+red[7];
}

__global__ void __launch_bounds__(256)
ln_kernel(const float* __restrict__ X, const float* __restrict__ gw,
          const float* __restrict__ bw, float* __restrict__ Y)
{
    __shared__ float red[8];
    const int row = blockIdx.x;
    const int tid = threadIdx.x;
    const size_t base = (size_t)row * Dsz + tid * 4;

    float4 v = *(const float4*)&X[base];
    float mean = block_sum(v.x + v.y + v.z + v.w, red) * (1.f / Dsz);
    float dx = v.x - mean, dy = v.y - mean, dz = v.z - mean, dw = v.w - mean;
    float var = block_sum(dx*dx + dy*dy + dz*dz + dw*dw, red) * (1.f / Dsz);
    float inv = rsqrtf(var + 1e-6f);

    float4 g4 = *(const float4*)&gw[tid * 4];
    float4 b4 = *(const float4*)&bw[tid * 4];
    float4 o;
    o.x = dx * inv * g4.x + b4.x;
    o.y = dy * inv * g4.y + b4.y;
    o.z = dz * inv * g4.z + b4.z;
    o.w = dw * inv * g4.w + b4.w;
    *(float4*)&Y[base] = o;
}

// ---------------- driver -----------------------------------------------------
extern "C" void kernel_launch(void* const* d_in, const int* in_sizes, int n_in,
                              void* d_out, int out_size)
{
    const float* hid  = (const float*)d_in[0];
    const float* Wq   = (const float*)d_in[1];
    const float* bq   = (const float*)d_in[2];
    const float* Wk   = (const float*)d_in[3];
    const float* bk   = (const float*)d_in[4];
    const float* Wv   = (const float*)d_in[5];
    const float* bv   = (const float*)d_in[6];
    const float* Wp   = (const float*)d_in[7];
    const float* bp   = (const float*)d_in[8];
    const float* g1   = (const float*)d_in[9];
    const float* be1  = (const float*)d_in[10];
    const float* W1   = (const float*)d_in[11];
    const float* b1   = (const float*)d_in[12];
    const float* W2   = (const float*)d_in[13];
    const float* b2   = (const float*)d_in[14];
    const float* g2   = (const float*)d_in[15];
    const float* be2  = (const float*)d_in[16];

    float *pX, *pQ, *pK, *pV, *pC, *pT, *pH;
    uint32_t *pAh, *pBh;
    cudaGetSymbolAddress((void**)&pX, g_X);
    cudaGetSymbolAddress((void**)&pQ, g_Q);
    cudaGetSymbolAddress((void**)&pK, g_K);
    cudaGetSymbolAddress((void**)&pV, g_V);
    cudaGetSymbolAddress((void**)&pC, g_C);
    cudaGetSymbolAddress((void**)&pT, g_T);
    cudaGetSymbolAddress((void**)&pH, g_Hb);
    cudaGetSymbolAddress((void**)&pAh, g_Ah);
    cudaGetSymbolAddress((void**)&pBh, g_Bh);

    cudaFuncSetAttribute(attn_kernel,
                         cudaFuncAttributeMaxDynamicSharedMemorySize, ATT_SMEM);
    cudaFuncSetAttribute(gemm_f16<false,false>,
                         cudaFuncAttributeMaxDynamicSharedMemorySize, GEMM_SMEM);
    cudaFuncSetAttribute(gemm_f16<false,true>,
                         cudaFuncAttributeMaxDynamicSharedMemorySize, GEMM_SMEM);
    cudaFuncSetAttribute(gemm_f16<true,false>,
                         cudaFuncAttributeMaxDynamicSharedMemorySize, GEMM_SMEM);

    const size_t hbytes = sizeof(float) * (size_t)MROWS * Dsz;
    cudaMemcpyAsync(pX, hid, hbytes, cudaMemcpyDeviceToDevice);

    dim3 gD(Dsz / 128, MROWS / 128);   // (8, 64)
    dim3 gF(Ff  / 128, MROWS / 128);   // (32, 64)
    dim3 gA(Ssz / 64, Bsz * Hh);       // (8, 256)

    const int nXp  = MROWS * Dsz / 2;          // packed words of X/C (4M)
    const int nHp  = MROWS * Ff / 2;           // packed words of H (16M)
    const int nWdd = (Dsz/2) * Dsz;            // packed words D x D (0.5M)
    const int nWdf = (Dsz/2) * Ff;             // D x F (2M)
    const int nWfd = (Ff/2)  * Dsz;            // F x D (2M)

    for (int l = 0; l < 4; ++l) {
        const float* wq = Wq + (size_t)l * Dsz * Dsz;
        const float* wk = Wk + (size_t)l * Dsz * Dsz;
        const float* wv = Wv + (size_t)l * Dsz * Dsz;
        const float* wp = Wp + (size_t)l * Dsz * Dsz;
        const float* w1 = W1 + (size_t)l * Dsz * Ff;
        const float* w2 = W2 + (size_t)l * Ff * Dsz;

        // QKV
        pack_a<<<nXp/256, 256>>>(pX, pAh, nXp);
        pack_w<<<nWdd/256, 256>>>(wq, pBh, nWdd, 10);
        gemm_f16<false,false><<<gD, 256, GEMM_SMEM>>>(pAh, pBh, bq + l*Dsz, nullptr, pQ, MROWS, Dsz, Dsz);
        pack_w<<<nWdd/256, 256>>>(wk, pBh, nWdd, 10);
        gemm_f16<false,false><<<gD, 256, GEMM_SMEM>>>(pAh, pBh, bk + l*Dsz, nullptr, pK, MROWS, Dsz, Dsz);
        pack_w<<<nWdd/256, 256>>>(wv, pBh, nWdd, 10);
        gemm_f16<false,false><<<gD, 256, GEMM_SMEM>>>(pAh, pBh, bv + l*Dsz, nullptr, pV, MROWS, Dsz, Dsz);

        attn_kernel<<<gA, 256, ATT_SMEM>>>(pQ, pK, pV, pC);

        // proj + LN1
        pack_a<<<nXp/256, 256>>>(pC, pAh, nXp);
        pack_w<<<nWdd/256, 256>>>(wp, pBh, nWdd, 10);
        gemm_f16<false,true ><<<gD, 256, GEMM_SMEM>>>(pAh, pBh, bp + l*Dsz, pX, pT, MROWS, Dsz, Dsz);
        ln_kernel<<<MROWS, 256>>>(pT, g1 + l*Dsz, be1 + l*Dsz, pX);

        // FFN1 (ReLU)
        pack_a<<<nXp/256, 256>>>(pX, pAh, nXp);
        pack_w<<<nWdf/256, 256>>>(w1, pBh, nWdf, 12);
        gemm_f16<true ,false><<<gF, 256, GEMM_SMEM>>>(pAh, pBh, b1 + l*Ff, nullptr, pH, MROWS, Ff, Dsz);

        // FFN2 + LN2
        pack_a<<<nHp/256, 256>>>(pH, pAh, nHp);
        pack_w<<<nWfd/256, 256>>>(w2, pBh, nWfd, 10);
        gemm_f16<false,true ><<<gD, 256, GEMM_SMEM>>>(pAh, pBh, b2 + l*Dsz, pX, pT, MROWS, Dsz, Ff);
        ln_kernel<<<MROWS, 256>>>(pT, g2 + l*Dsz, be2 + l*Dsz, pX);
    }

    cudaMemcpyAsync((float*)d_out, pX, hbytes, cudaMemcpyDeviceToDevice);
}